// round 1
// baseline (speedup 1.0000x reference)
#include <cuda_runtime.h>
#include <math.h>

#define SETS 32   // B*M
#define NI   128  // N
#define DD   32   // D
#define KK   64   // 2D
#define HH   64   // H

// Scratch (allocation-free rule: __device__ globals)
__device__ __align__(16) float g_x1[SETS * NI * DD];
__device__ __align__(16) float g_A [SETS * NI * KK];
__device__ __align__(16) float g_B [SETS * NI * KK];
__device__ float g_mask[SETS * NI];
__device__ float g_v2[KK];
__device__ float g_c2;

__device__ __forceinline__ float gelu_t(float x) {
    // jax.nn.gelu approximate=True: 0.5*x*(1+tanh(0.7978845608*(x+0.044715 x^3)))
    float u = x * fmaf(0.044715f * 0.7978845608028654f, x * x, 0.7978845608028654f);
    float th;
    asm("tanh.approx.f32 %0, %1;" : "=f"(th) : "f"(u));
    float hx = 0.5f * x;
    return fmaf(hx, th, hx);
}

__device__ __forceinline__ float block_sum_128(float v, float* sh4) {
    #pragma unroll
    for (int o = 16; o > 0; o >>= 1) v += __shfl_down_sync(0xffffffffu, v, o);
    int lane = threadIdx.x & 31, w = threadIdx.x >> 5;
    if (lane == 0) sh4[w] = v;
    __syncthreads();
    float r = sh4[0] + sh4[1] + sh4[2] + sh4[3];
    __syncthreads();
    return r;
}

// Kernel 1: per-set stats + set_norm + MLP1 + A/B precompute. 32 blocks x 128 threads.
__global__ __launch_bounds__(128) void k1_prep(
    const float* __restrict__ x, const float* __restrict__ xsz,
    const float* __restrict__ W1a, const float* __restrict__ b1a,
    const float* __restrict__ W1b, const float* __restrict__ b1b,
    const float* __restrict__ W2a, const float* __restrict__ b2a,
    const float* __restrict__ W2b, const float* __restrict__ b2b,
    const float* __restrict__ w3)
{
    const int s = blockIdx.x;
    const int n = threadIdx.x;

    __shared__ float red[4];
    __shared__ float sW1a[DD * KK];
    __shared__ float sb1a[KK];
    __shared__ float sW1b[KK * DD];
    __shared__ float sb1b[DD];
    __shared__ float sW2a[DD * KK];
    __shared__ float sb2a[KK];

    for (int i = n; i < DD * KK; i += 128) {
        sW1a[i] = W1a[i];
        sW1b[i] = W1b[i];
        sW2a[i] = W2a[i];
    }
    for (int i = n; i < KK; i += 128) { sb1a[i] = b1a[i]; sb2a[i] = b2a[i]; }
    for (int i = n; i < DD; i += 128) sb1b[i] = b1b[i];

    // Load row n of x, compute mask + partial sum
    float xr[DD];
    const float* xp = x + ((size_t)s * NI + n) * DD;
    float lsum = 0.f;
    int anynz = 0;
    #pragma unroll
    for (int d = 0; d < DD; d++) {
        xr[d] = xp[d];
        lsum += xr[d];
        anynz |= (xr[d] != 0.0f);
    }
    const float mk = anynz ? 1.0f : 0.0f;

    __syncthreads();  // weights loaded; also before red usage
    const float tot   = block_sum_128(lsum, red);
    const float denom = xsz[s >> 3] * (float)DD;
    const float mean  = tot / denom;

    float lv = 0.f;
    #pragma unroll
    for (int d = 0; d < DD; d++) { float df = xr[d] - mean; lv = fmaf(df, df, lv); }
    lv *= mk;
    const float var = block_sum_128(lv, red);
    const float inv = mk / (sqrtf(var / denom) + 1e-8f);

    float xn[DD];
    #pragma unroll
    for (int d = 0; d < DD; d++) xn[d] = (xr[d] - mean) * inv;

    // MLP1 fused: x1[d] = mk*(b1b[d] + sum_k gelu(b1a[k]+xn.W1a[:,k]) * W1b[k,d])
    float x1a[DD];
    #pragma unroll
    for (int d = 0; d < DD; d++) x1a[d] = sb1b[d];
    for (int k = 0; k < KK; k++) {
        float aa = sb1a[k];
        #pragma unroll
        for (int d = 0; d < DD; d++) aa = fmaf(xn[d], sW1a[d * KK + k], aa);
        float g = gelu_t(aa);
        #pragma unroll
        for (int d = 0; d < DD; d++) x1a[d] = fmaf(g, sW1b[k * DD + d], x1a[d]);
    }
    #pragma unroll
    for (int d = 0; d < DD; d++) x1a[d] *= mk;

    float* px1 = g_x1 + ((size_t)s * NI + n) * DD;
    #pragma unroll
    for (int d = 0; d < DD; d++) px1[d] = x1a[d];

    // A[k] = b2a[k] + x1 . W2a[:,k] ;  B[k] = xn . W2a[:,k]
    float* pA = g_A + ((size_t)s * NI + n) * KK;
    float* pB = g_B + ((size_t)s * NI + n) * KK;
    for (int k = 0; k < KK; k++) {
        float a = sb2a[k], bb = 0.f;
        #pragma unroll
        for (int d = 0; d < DD; d++) {
            float w = sW2a[d * KK + k];
            a  = fmaf(x1a[d], w, a);
            bb = fmaf(xn[d],  w, bb);
        }
        pA[k] = a;
        pB[k] = bb;
    }
    g_mask[s * NI + n] = mk;

    if (s == 0) {
        if (n < KK) {
            float a = 0.f;
            for (int h = 0; h < HH; h++) a = fmaf(W2b[n * HH + h], w3[h], a);
            g_v2[n] = a;
        }
        if (n == KK) {
            float a = 0.f;
            for (int h = 0; h < HH; h++) a = fmaf(b2b[h], w3[h], a);
            g_c2 = a;
        }
    }
}

// Kernel 2: pairwise gelu-dot + aggregation. Grid = SETS*8 blocks (j-tiles of 16), 128 threads.
#define JT 16
__global__ __launch_bounds__(128) void k2_pair(
    const float* __restrict__ x, const float* __restrict__ b3,
    float* __restrict__ out)
{
    const int blk = blockIdx.x;
    const int s  = blk >> 3;
    const int j0 = (blk & 7) * JT;
    const int tid = threadIdx.x;  // thread == row i

    __shared__ float sB[JT * KK];     // 4 KB
    __shared__ float sV[KK];
    __shared__ float sX1[NI * DD];    // 16 KB
    __shared__ float sS[JT * NI];     // 8 KB
    __shared__ float sMk[JT];
    __shared__ float sc2;

    const float* pB = g_B + ((size_t)s * NI + j0) * KK;
    for (int i = tid; i < JT * KK; i += 128) sB[i] = pB[i];
    const float* pX1 = g_x1 + (size_t)s * NI * DD;
    for (int i = tid; i < NI * DD; i += 128) sX1[i] = pX1[i];
    if (tid < KK) sV[tid] = g_v2[tid];
    if (tid == KK) sc2 = g_c2;
    if (tid < JT) sMk[tid] = g_mask[s * NI + j0 + tid];

    // A row -> registers
    float a[KK];
    const float4* pA = (const float4*)(g_A + ((size_t)s * NI + tid) * KK);
    #pragma unroll
    for (int q = 0; q < KK / 4; q++) {
        float4 v = pA[q];
        a[4 * q + 0] = v.x; a[4 * q + 1] = v.y;
        a[4 * q + 2] = v.z; a[4 * q + 3] = v.w;
    }
    __syncthreads();

    const float c2 = sc2;
    for (int j = 0; j < JT; j++) {
        float acc = c2;
        const float* br = &sB[j * KK];
        #pragma unroll
        for (int k = 0; k < KK; k++) {
            float t = a[k] - br[k];
            acc = fmaf(gelu_t(t), sV[k], acc);
        }
        sS[j * NI + tid] = acc;
    }
    __syncthreads();

    // Phase 2: out[j,d] = sum_i S[j,i] * x1[i,d]  (+ b3 + x) * mask
    const int d = tid & 31;
    const int w = tid >> 5;
    const float b3v = b3[0];
    #pragma unroll
    for (int r = 0; r < 4; r++) {
        const int j = r * 4 + w;
        float acc = 0.f;
        const float* srow = &sS[j * NI];
        #pragma unroll 8
        for (int i = 0; i < NI; i++) acc = fmaf(srow[i], sX1[i * DD + d], acc);
        const int jg = j0 + j;
        const size_t oidx = ((size_t)s * NI + jg) * DD + d;
        out[oidx] = (acc + b3v + x[oidx]) * sMk[j];
    }
}

extern "C" void kernel_launch(void* const* d_in, const int* in_sizes, int n_in,
                              void* d_out, int out_size) {
    const float* x    = (const float*)d_in[0];
    const float* xsz  = (const float*)d_in[1];
    const float* W1a  = (const float*)d_in[2];
    const float* b1a  = (const float*)d_in[3];
    const float* W1b  = (const float*)d_in[4];
    const float* b1b  = (const float*)d_in[5];
    const float* W2a  = (const float*)d_in[6];
    const float* b2a  = (const float*)d_in[7];
    const float* W2b  = (const float*)d_in[8];
    const float* b2b  = (const float*)d_in[9];
    const float* w3   = (const float*)d_in[10];
    const float* b3   = (const float*)d_in[11];
    float* out = (float*)d_out;

    k1_prep<<<SETS, 128>>>(x, xsz, W1a, b1a, W1b, b1b, W2a, b2a, W2b, b2b, w3);
    k2_pair<<<SETS * 8, 128>>>(x, b3, out);
}